// round 1
// baseline (speedup 1.0000x reference)
#include <cuda_runtime.h>
#include <cstdint>

// MultiLIF: I[B=32, L=2048, K=512] -> (spikes[B,L,K], spike_series[B,L,K])
// d_out layout: spikes first (B*L*K floats), then spike_series (B*L*K floats).
//
// Per-neuron recurrence (t = 0..L-1), state v,a,n starting at 0:
//   th  = 1 + 1.5*a
//   v   = v - v/20 + I[b,t,k]
//   s   = (v >= th) ? 1 : 0          // straight-through value == s_hard exactly
//   n  += s
//   out_spikes[b,t,k] = s ; out_series[b,t,k] = n
//   v   = v*(1-s) + (-0.5)*s
//   a   = a - a/100 + s
//
// Divisions are forced to IEEE round-to-nearest (__fdiv_rn) to match XLA,
// which does NOT strength-reduce division by non-power-of-two constants.

static constexpr int B_ = 32;
static constexpr int L_ = 2048;
static constexpr int K_ = 512;
static constexpr int NEURONS = B_ * K_;      // 16384
static constexpr int UNROLL = 16;            // prefetch depth (timesteps)

__device__ __forceinline__ void lif_steps(
    const float* __restrict__ buf,
    float* __restrict__ sp, float* __restrict__ np,
    int64_t t0K,                 // t0 * K (element offset of this batch)
    float& v, float& a, float& n)
{
#pragma unroll
    for (int u = 0; u < UNROLL; u++) {
        float It = buf[u];
        float th = 1.0f + 1.5f * a;
        v = (v - __fdiv_rn(v, 20.0f)) + It;
        float s = (v >= th) ? 1.0f : 0.0f;
        n = n + s;
        int64_t off = t0K + (int64_t)u * K_;
        __stcs(sp + off, s);
        __stcs(np + off, n);
        v = v * (1.0f - s) + (-0.5f) * s;
        a = (a - __fdiv_rn(a, 100.0f)) + s;
    }
}

__device__ __forceinline__ void load_batch(
    const float* __restrict__ ip, int64_t t0K, float* __restrict__ buf)
{
#pragma unroll
    for (int u = 0; u < UNROLL; u++)
        buf[u] = __ldcs(ip + t0K + (int64_t)u * K_);
}

__global__ __launch_bounds__(128, 1)
void MultiLIF_kernel(const float* __restrict__ I,
                     float* __restrict__ spikes,
                     float* __restrict__ series)
{
    int gid = blockIdx.x * blockDim.x + threadIdx.x;   // 0..16383, exact
    int b = gid >> 9;           // /512
    int k = gid & (K_ - 1);     // %512

    int64_t base = (int64_t)b * L_ * K_ + k;
    const float* ip = I + base;
    float* sp = spikes + base;
    float* np = series + base;

    float v = 0.0f, a = 0.0f, n = 0.0f;

    float buf0[UNROLL], buf1[UNROLL];

    // prologue: load batch 0
    load_batch(ip, 0, buf0);

    // ping-pong: prefetch next batch while computing current
    for (int t0 = 0; t0 < L_; t0 += 2 * UNROLL) {
        // prefetch batch t0+U into buf1
        load_batch(ip, (int64_t)(t0 + UNROLL) * K_, buf1);
        // compute batch t0 from buf0
        lif_steps(buf0, sp, np, (int64_t)t0 * K_, v, a, n);
        // prefetch batch t0+2U into buf0 (skip past the end)
        if (t0 + 2 * UNROLL < L_)
            load_batch(ip, (int64_t)(t0 + 2 * UNROLL) * K_, buf0);
        // compute batch t0+U from buf1
        lif_steps(buf1, sp, np, (int64_t)(t0 + UNROLL) * K_, v, a, n);
    }
}

extern "C" void kernel_launch(void* const* d_in, const int* in_sizes, int n_in,
                              void* d_out, int out_size)
{
    const float* I = (const float*)d_in[0];
    float* spikes = (float*)d_out;
    float* series = (float*)d_out + (int64_t)B_ * L_ * K_;

    dim3 block(128);
    dim3 grid(NEURONS / 128);   // 128 blocks, all in wave 1 on 148 SMs
    MultiLIF_kernel<<<grid, block>>>(I, spikes, series);
}

// round 2
// speedup vs baseline: 1.4468x; 1.4468x over previous
#include <cuda_runtime.h>
#include <cstdint>

// MultiLIF: I[B=32, L=2048, K=512] -> (spikes[B,L,K], spike_series[B,L,K])
// d_out layout: spikes first (B*L*K floats), then spike_series.
//
// Round-2 change: replace __fdiv_rn (which carries an FCHK slow-path branch,
// ~56 cyc BSSY/BSYNC envelope per divide, 2 divides on the carried chain) with
// the branch-free Markstein correctly-rounded constant division:
//   y = RN(1/b); q0 = RN(x*y); r = fma(-b,q0,x); q = fma(r,y,q0)  == RN(x/b)
// Bit-identical to IEEE division for all normal cases (divisors 20, 100;
// |v|,|a| bounded O(100); zeros round-trip exactly). rel_err stays 0.

static constexpr int B_ = 32;
static constexpr int L_ = 2048;
static constexpr int K_ = 512;
static constexpr int NEURONS = B_ * K_;      // 16384
static constexpr int UNROLL = 16;            // prefetch depth (timesteps)

__device__ __forceinline__ float div_const_rn(float x, float b, float y)
{
    // Markstein: correctly-rounded x/b given y = RN(1/b). 3 ops, branch-free.
    float q0 = __fmul_rn(x, y);
    float r  = __fmaf_rn(-b, q0, x);
    return __fmaf_rn(r, y, q0);
}

__device__ __forceinline__ void lif_steps(
    const float* __restrict__ buf,
    float* __restrict__ sp, float* __restrict__ np,
    int64_t t0K,
    float& v, float& a, float& n)
{
#pragma unroll
    for (int u = 0; u < UNROLL; u++) {
        float It = buf[u];
        float th = 1.0f + 1.5f * a;                       // FFMA (matches XLA)
        v = (v - div_const_rn(v, 20.0f, 0.05f)) + It;     // exact RN(v/20)
        bool fire = (v >= th);
        float s = fire ? 1.0f : 0.0f;
        n = n + s;
        int64_t off = t0K + (int64_t)u * K_;
        __stcs(sp + off, s);
        __stcs(np + off, n);
        v = fire ? -0.5f : v;                             // == v*(1-s)+(-0.5)*s
        a = (a - div_const_rn(a, 100.0f, 0.01f)) + s;     // exact RN(a/100)
    }
}

__device__ __forceinline__ void load_batch(
    const float* __restrict__ ip, int64_t t0K, float* __restrict__ buf)
{
#pragma unroll
    for (int u = 0; u < UNROLL; u++)
        buf[u] = __ldcs(ip + t0K + (int64_t)u * K_);
}

__global__ __launch_bounds__(128, 1)
void MultiLIF_kernel(const float* __restrict__ I,
                     float* __restrict__ spikes,
                     float* __restrict__ series)
{
    int gid = blockIdx.x * blockDim.x + threadIdx.x;   // 0..16383
    int b = gid >> 9;           // /512
    int k = gid & (K_ - 1);     // %512

    int64_t base = (int64_t)b * L_ * K_ + k;
    const float* ip = I + base;
    float* sp = spikes + base;
    float* np = series + base;

    float v = 0.0f, a = 0.0f, n = 0.0f;

    float buf0[UNROLL], buf1[UNROLL];

    load_batch(ip, 0, buf0);

    for (int t0 = 0; t0 < L_; t0 += 2 * UNROLL) {
        load_batch(ip, (int64_t)(t0 + UNROLL) * K_, buf1);
        lif_steps(buf0, sp, np, (int64_t)t0 * K_, v, a, n);
        if (t0 + 2 * UNROLL < L_)
            load_batch(ip, (int64_t)(t0 + 2 * UNROLL) * K_, buf0);
        lif_steps(buf1, sp, np, (int64_t)(t0 + UNROLL) * K_, v, a, n);
    }
}

extern "C" void kernel_launch(void* const* d_in, const int* in_sizes, int n_in,
                              void* d_out, int out_size)
{
    const float* I = (const float*)d_in[0];
    float* spikes = (float*)d_out;
    float* series = (float*)d_out + (int64_t)B_ * L_ * K_;

    dim3 block(128);
    dim3 grid(NEURONS / 128);
    MultiLIF_kernel<<<grid, block>>>(I, spikes, series);
}